// round 1
// baseline (speedup 1.0000x reference)
#include <cuda_runtime.h>

#define KC 16
#define MT 64
#define OPAD 160
#define SP 153   // stage pitch (odd -> no systematic bank conflicts)

// Block: 256 threads = 16 m-quads (4 pixels each, float4) x 16 o-groups.
// o-group oq owns outputs o = oq + 16*j, j=0..9 (o<80: cls, 80..143: reg, 144: obj).
__global__ __launch_bounds__(256) void pred_level_kernel(
    const float* __restrict__ clsF0, const float* __restrict__ regF0,
    const float* __restrict__ obj_w, const float* __restrict__ obj_b,
    const float* __restrict__ cls_w, const float* __restrict__ cls_b,
    const float* __restrict__ reg_w, const float* __restrict__ reg_b,
    float* __restrict__ out, int M, int W, float stride, int moff)
{
    __shared__ union SU {
        struct { float cls_s[KC * MT]; float reg_s[KC * MT]; float w_s[KC * OPAD]; } lp;
        float stage[MT * SP];
    } sm;

    const int b  = blockIdx.y;
    const int m0 = blockIdx.x * MT;
    const int mvalid = min(MT, M - m0);
    const int t  = threadIdx.x;
    const int mq = t & 15;
    const int oq = t >> 4;

    const float* clsF = clsF0 + (size_t)b * 256 * M;
    const float* regF = regF0 + (size_t)b * 256 * M;

    float accC[5][4], accR[4][4], accO[4];
    #pragma unroll
    for (int j = 0; j < 5; j++)
        #pragma unroll
        for (int e = 0; e < 4; e++) accC[j][e] = 0.f;
    #pragma unroll
    for (int j = 0; j < 4; j++)
        #pragma unroll
        for (int e = 0; e < 4; e++) accR[j][e] = 0.f;
    #pragma unroll
    for (int e = 0; e < 4; e++) accO[e] = 0.f;

    // Zero w_s once: pad columns (o = 145..159) must stay 0 through all chunks.
    for (int i = t; i < KC * OPAD; i += 256) sm.lp.w_s[i] = 0.f;

    const int kk   = t >> 4;         // k row this thread loads (0..15)
    const int mloc = (t & 15) * 4;   // m offset this thread loads (float4)

    for (int k0 = 0; k0 < 256; k0 += KC) {
        __syncthreads();  // previous chunk fully consumed (also orders initial w_s zero-fill)

        // ---- stage feature chunk [KC][MT] for both tensors ----
        {
            const float* pc = clsF + (size_t)(k0 + kk) * M + m0 + mloc;
            const float* pr = regF + (size_t)(k0 + kk) * M + m0 + mloc;
            float4 c4, r4;
            if (mloc + 4 <= mvalid) {
                c4 = *(const float4*)pc;
                r4 = *(const float4*)pr;
            } else {
                c4.x = (mloc + 0 < mvalid) ? pc[0] : 0.f;
                c4.y = (mloc + 1 < mvalid) ? pc[1] : 0.f;
                c4.z = (mloc + 2 < mvalid) ? pc[2] : 0.f;
                c4.w = (mloc + 3 < mvalid) ? pc[3] : 0.f;
                r4.x = (mloc + 0 < mvalid) ? pr[0] : 0.f;
                r4.y = (mloc + 1 < mvalid) ? pr[1] : 0.f;
                r4.z = (mloc + 2 < mvalid) ? pr[2] : 0.f;
                r4.w = (mloc + 3 < mvalid) ? pr[3] : 0.f;
            }
            *(float4*)&sm.lp.cls_s[kk * MT + mloc] = c4;
            *(float4*)&sm.lp.reg_s[kk * MT + mloc] = r4;
        }

        // ---- stage weight chunk, transposed to k-major [KC][OPAD] ----
        for (int idx = t; idx < 145 * 4; idx += 256) {
            int o = idx >> 2, q = idx & 3;
            const float* wrow = (o < 80)  ? (cls_w + o * 256)
                              : (o < 144) ? (reg_w + (o - 80) * 256)
                                          : obj_w;
            float4 wv = *(const float4*)(wrow + k0 + q * 4);
            sm.lp.w_s[(q * 4 + 0) * OPAD + o] = wv.x;
            sm.lp.w_s[(q * 4 + 1) * OPAD + o] = wv.y;
            sm.lp.w_s[(q * 4 + 2) * OPAD + o] = wv.z;
            sm.lp.w_s[(q * 4 + 3) * OPAD + o] = wv.w;
        }
        __syncthreads();

        // ---- compute ----
        #pragma unroll
        for (int k = 0; k < KC; k++) {
            float4 c4 = *(const float4*)&sm.lp.cls_s[k * MT + mq * 4];
            float4 r4 = *(const float4*)&sm.lp.reg_s[k * MT + mq * 4];
            const float* wr = &sm.lp.w_s[k * OPAD + oq];
            #pragma unroll
            for (int j = 0; j < 5; j++) {
                float w = wr[16 * j];
                accC[j][0] = fmaf(w, c4.x, accC[j][0]);
                accC[j][1] = fmaf(w, c4.y, accC[j][1]);
                accC[j][2] = fmaf(w, c4.z, accC[j][2]);
                accC[j][3] = fmaf(w, c4.w, accC[j][3]);
            }
            #pragma unroll
            for (int j = 0; j < 4; j++) {
                float w = wr[16 * (5 + j)];
                accR[j][0] = fmaf(w, r4.x, accR[j][0]);
                accR[j][1] = fmaf(w, r4.y, accR[j][1]);
                accR[j][2] = fmaf(w, r4.z, accR[j][2]);
                accR[j][3] = fmaf(w, r4.w, accR[j][3]);
            }
            {
                float w = wr[16 * 9];   // o = 144 + oq (obj if oq==0, zero pad otherwise)
                accO[0] = fmaf(w, r4.x, accO[0]);
                accO[1] = fmaf(w, r4.y, accO[1]);
                accO[2] = fmaf(w, r4.z, accO[2]);
                accO[3] = fmaf(w, r4.w, accO[3]);
            }
        }
    }

    __syncthreads();  // all compute reads done; stage aliases the loop buffers

    // ---- epilogue: write accumulators (+bias) into the output-layout stage ----
    #pragma unroll
    for (int j = 0; j < 5; j++) {
        int o = oq + 16 * j;
        float bias = __ldg(&cls_b[o]);
        #pragma unroll
        for (int e = 0; e < 4; e++)
            sm.stage[(mq * 4 + e) * SP + 1 + o] = accC[j][e] + bias;
    }
    #pragma unroll
    for (int j = 0; j < 4; j++) {
        int r = oq + 16 * j;
        float bias = __ldg(&reg_b[r]);
        #pragma unroll
        for (int e = 0; e < 4; e++)
            sm.stage[(mq * 4 + e) * SP + 81 + r] = accR[j][e] + bias;
    }
    if (oq == 0) {
        float bias = __ldg(obj_b);
        #pragma unroll
        for (int e = 0; e < 4; e++)
            sm.stage[(mq * 4 + e) * SP + 0] = accO[e] + bias;
    }
    __syncthreads();

    // ---- DFL decode + box: one (m, side) per thread ----
    {
        int m = t >> 2, f = t & 3;
        const float* row = &sm.stage[m * SP + 81 + 16 * f];
        float mx = row[0];
        #pragma unroll
        for (int i = 1; i < 16; i++) mx = fmaxf(mx, row[i]);
        float se = 0.f, sw = 0.f;
        #pragma unroll
        for (int i = 0; i < 16; i++) {
            float ev = __expf(row[i] - mx);
            se += ev;
            sw = fmaf(ev, (float)i, sw);
        }
        float d = (sw / se) * (16.0f / 15.0f);   // proj[i] = i * 16/15
        int mg = m0 + m;
        int hh = mg / W, ww = mg - hh * W;
        float ax = ((float)ww + 0.5f) * stride;
        float ay = ((float)hh + 0.5f) * stride;
        float ds = d * stride;
        float v = (f == 0) ? (ax - ds)
                : (f == 1) ? (ay - ds)
                : (f == 2) ? (ax + ds)
                           : (ay + ds);
        sm.stage[m * SP + 145 + f] = v;
    }
    __syncthreads();

    // ---- coalesced contiguous store of the 64x149 slab ----
    float* outp = out + ((size_t)b * 8400 + moff + m0) * 149;
    int tot = mvalid * 149;
    for (int idx = t; idx < tot; idx += 256) {
        int m  = idx / 149;
        int ch = idx - m * 149;
        outp[idx] = sm.stage[m * SP + ch];
    }
}

extern "C" void kernel_launch(void* const* d_in, const int* in_sizes, int n_in,
                              void* d_out, int out_size)
{
    // Disambiguate feature-tensor ordering at runtime:
    //   dict order:      cls0, reg0, cls1, reg1, cls2, reg2   (sizes[1] == sizes[0])
    //   signature order: cls0, cls1, cls2, reg0, reg1, reg2   (sizes[1] <  sizes[0])
    const float* clsf[3];
    const float* regf[3];
    if (in_sizes[1] == in_sizes[0]) {
        clsf[0] = (const float*)d_in[0]; regf[0] = (const float*)d_in[1];
        clsf[1] = (const float*)d_in[2]; regf[1] = (const float*)d_in[3];
        clsf[2] = (const float*)d_in[4]; regf[2] = (const float*)d_in[5];
    } else {
        clsf[0] = (const float*)d_in[0]; regf[0] = (const float*)d_in[3];
        clsf[1] = (const float*)d_in[1]; regf[1] = (const float*)d_in[4];
        clsf[2] = (const float*)d_in[2]; regf[2] = (const float*)d_in[5];
    }

    const int   Ms[3]      = {6400, 1600, 400};
    const int   Ws[3]      = {80, 40, 20};
    const int   moffs[3]   = {0, 6400, 8000};
    const float strides[3] = {8.f, 16.f, 32.f};

    int B = in_sizes[0] / (256 * 6400);   // = 16

    for (int l = 0; l < 3; l++) {
        const float* ow = (const float*)d_in[6  + 6 * l];
        const float* ob = (const float*)d_in[7  + 6 * l];
        const float* cw = (const float*)d_in[8  + 6 * l];
        const float* cb = (const float*)d_in[9  + 6 * l];
        const float* rw = (const float*)d_in[10 + 6 * l];
        const float* rb = (const float*)d_in[11 + 6 * l];
        dim3 grid((Ms[l] + MT - 1) / MT, B);
        pred_level_kernel<<<grid, 256>>>(clsf[l], regf[l], ow, ob, cw, cb, rw, rb,
                                         (float*)d_out, Ms[l], Ws[l], strides[l], moffs[l]);
    }
}

// round 3
// speedup vs baseline: 2.4874x; 2.4874x over previous
#include <cuda_runtime.h>
#include <cuda_bf16.h>
#include <cstdint>

#define WPITCHB 528                  // weight smem row pitch: 264 bf16
#define FPITCHB 272                  // feat smem row pitch: 136 bf16
#define FBUFB   8704                 // one feat tensor chunk: 32 k-rows * 272 B
#define WOFF    0                    // weights: 160 rows * 528 B = 84480 (aliased by stage)
#define FOFF    84480                // feat: 2 bufs * 2 tensors * 8704 = 34816
#define SMEM_TOTAL (84480 + 4 * FBUFB)   // 119296 B
#define SP 153                       // epilogue stage pitch (floats)

struct Params {
    const float* clsF[3]; const float* regF[3];
    const float* ow[3]; const float* ob[3];
    const float* cw[3]; const float* cb[3];
    const float* rw[3]; const float* rb[3];
};

extern __shared__ char smch[];

__device__ __forceinline__ uint32_t smu32(const void* p) {
    uint32_t a;
    asm("{ .reg .u64 t; cvta.to.shared.u64 t, %1; cvt.u32.u64 %0, t; }" : "=r"(a) : "l"(p));
    return a;
}
__device__ __forceinline__ uint32_t pkbf(float a, float b) {
    __nv_bfloat162 h = __floats2bfloat162_rn(a, b);
    return *reinterpret_cast<uint32_t*>(&h);
}
__device__ __forceinline__ void ldsm4(uint32_t* r, uint32_t a) {
    asm volatile("ldmatrix.sync.aligned.m8n8.x4.shared.b16 {%0,%1,%2,%3}, [%4];"
                 : "=r"(r[0]), "=r"(r[1]), "=r"(r[2]), "=r"(r[3]) : "r"(a));
}
__device__ __forceinline__ void ldsm4t(uint32_t* r, uint32_t a) {
    asm volatile("ldmatrix.sync.aligned.m8n8.x4.trans.shared.b16 {%0,%1,%2,%3}, [%4];"
                 : "=r"(r[0]), "=r"(r[1]), "=r"(r[2]), "=r"(r[3]) : "r"(a));
}
__device__ __forceinline__ void mma16816(float* d, const uint32_t* a, const uint32_t* b) {
    asm volatile("mma.sync.aligned.m16n8k16.row.col.f32.bf16.bf16.f32 "
                 "{%0,%1,%2,%3}, {%4,%5,%6,%7}, {%8,%9}, {%0,%1,%2,%3};"
                 : "+f"(d[0]), "+f"(d[1]), "+f"(d[2]), "+f"(d[3])
                 : "r"(a[0]), "r"(a[1]), "r"(a[2]), "r"(a[3]), "r"(b[0]), "r"(b[1]));
}

__global__ __launch_bounds__(256, 1) void pred_mma_kernel(Params P, float* __restrict__ out)
{
    const int t = threadIdx.x, lane = t & 31, wid = t >> 5;
    const int wpx = wid & 3, wo = wid >> 2;   // 4 px-groups x 2 o-groups
    const int tb = blockIdx.x, b = blockIdx.y;

    int l, tile;
    if (tb < 50)      { l = 0; tile = tb; }
    else if (tb < 63) { l = 1; tile = tb - 50; }
    else              { l = 2; tile = tb - 63; }
    const int   Ms[3]    = {6400, 1600, 400};
    const int   Wg[3]    = {80, 40, 20};
    const int   moffs[3] = {0, 6400, 8000};
    const float strs[3]  = {8.f, 16.f, 32.f};
    const int M = Ms[l], W = Wg[l], moff = moffs[l];
    const float stride = strs[l];
    const int m0 = tile * 128;
    const int mvalid = min(128, M - m0);

    const float* clsF = P.clsF[l] + (size_t)b * 256 * M;
    const float* regF = P.regF[l] + (size_t)b * 256 * M;
    const uint32_t sb = smu32(smch);

    // ---- stage weights resident: rows 0..79 = cls, 80..143 = reg, 144 = obj, 145..159 = 0 ----
    {
        const float* cw = P.cw[l];
        const float* rw = P.rw[l];
        const float* ow = P.ow[l];
        #pragma unroll 4
        for (int i = t; i < 160 * 64; i += 256) {
            int o = i >> 6, q = i & 63;
            float4 v = make_float4(0.f, 0.f, 0.f, 0.f);
            if (o < 80)        v = *(const float4*)(cw + o * 256 + q * 4);
            else if (o < 144)  v = *(const float4*)(rw + (o - 80) * 256 + q * 4);
            else if (o == 144) v = *(const float4*)(ow + q * 4);
            *(uint2*)(smch + WOFF + o * WPITCHB + q * 8) =
                make_uint2(pkbf(v.x, v.y), pkbf(v.z, v.w));
        }
    }
    // ---- stage feat chunk 0 into buf 0 ----
    #pragma unroll
    for (int it = 0; it < 4; it++) {
        int i = t + it * 256;
        int k = i >> 5, q = i & 31, px = q * 4;
        float4 vc = make_float4(0.f, 0.f, 0.f, 0.f), vr = vc;
        if (px < mvalid) {
            vc = *(const float4*)(clsF + (size_t)k * M + m0 + px);
            vr = *(const float4*)(regF + (size_t)k * M + m0 + px);
        }
        char* p = smch + FOFF + k * FPITCHB + q * 8;
        *(uint2*)(p)         = make_uint2(pkbf(vc.x, vc.y), pkbf(vc.z, vc.w));
        *(uint2*)(p + FBUFB) = make_uint2(pkbf(vr.x, vr.y), pkbf(vr.z, vr.w));
    }
    __syncthreads();

    float acc[2][10][4];
    #pragma unroll
    for (int mt = 0; mt < 2; mt++)
        #pragma unroll
        for (int nt = 0; nt < 10; nt++)
            #pragma unroll
            for (int j = 0; j < 4; j++) acc[mt][nt][j] = 0.f;

    // per-lane ldmatrix base addresses
    const uint32_t wlane = sb + WOFF
        + (uint32_t)(wo * 80 + (lane & 7) + (lane >> 4) * 8) * WPITCHB
        + (uint32_t)((lane >> 3) & 1) * 16;
    const uint32_t flane = sb + FOFF + (uint32_t)wo * FBUFB
        + (uint32_t)((lane & 7) + ((lane >> 4) & 1) * 8) * FPITCHB
        + (uint32_t)(wpx * 32 + ((lane >> 3) & 1) * 8) * 2;

    for (int c = 0; c < 8; c++) {
        const int buf = c & 1;
        float4 pc[4], pr[4];
        if (c < 7) {                     // prefetch chunk c+1 into registers
            int kb = (c + 1) * 32;
            #pragma unroll
            for (int it = 0; it < 4; it++) {
                int i = t + it * 256;
                int k = i >> 5, q = i & 31, px = q * 4;
                if (px < mvalid) {
                    pc[it] = *(const float4*)(clsF + (size_t)(kb + k) * M + m0 + px);
                    pr[it] = *(const float4*)(regF + (size_t)(kb + k) * M + m0 + px);
                } else {
                    pc[it] = make_float4(0.f, 0.f, 0.f, 0.f);
                    pr[it] = pc[it];
                }
            }
        }
        // compute chunk c
        const uint32_t fb = flane + (uint32_t)buf * (2 * FBUFB);
        #pragma unroll
        for (int ks = 0; ks < 2; ks++) {
            uint32_t af[2][4];
            ldsm4t(af[0], fb + ks * 16 * FPITCHB);
            ldsm4t(af[1], fb + ks * 16 * FPITCHB + 32);
            const uint32_t kbyte = (uint32_t)(c * 32 + ks * 16) * 2;
            #pragma unroll
            for (int n2 = 0; n2 < 5; n2++) {
                uint32_t bf[4];
                ldsm4(bf, wlane + n2 * 16 * WPITCHB + kbyte);
                mma16816(acc[0][2 * n2],     af[0], bf);
                mma16816(acc[1][2 * n2],     af[1], bf);
                mma16816(acc[0][2 * n2 + 1], af[0], bf + 2);
                mma16816(acc[1][2 * n2 + 1], af[1], bf + 2);
            }
        }
        if (c < 7) {                     // commit prefetch into other buffer
            #pragma unroll
            for (int it = 0; it < 4; it++) {
                int i = t + it * 256;
                int k = i >> 5, q = i & 31;
                char* p = smch + FOFF + (buf ^ 1) * (2 * FBUFB) + k * FPITCHB + q * 8;
                *(uint2*)(p)         = make_uint2(pkbf(pc[it].x, pc[it].y), pkbf(pc[it].z, pc[it].w));
                *(uint2*)(p + FBUFB) = make_uint2(pkbf(pr[it].x, pr[it].y), pkbf(pr[it].z, pr[it].w));
            }
        }
        __syncthreads();
    }

    // ---- epilogue: fragments (+bias) -> stage (aliases weights) -> DFL -> store ----
    float* stg = reinterpret_cast<float*>(smch);
    {
        const float* cb = P.cb[l];
        const float* rb = P.rb[l];
        const float* ob = P.ob[l];
        #pragma unroll
        for (int mt = 0; mt < 2; mt++)
            #pragma unroll
            for (int nt = 0; nt < 10; nt++)
                #pragma unroll
                for (int j = 0; j < 4; j++) {
                    int px = wpx * 32 + mt * 16 + (lane >> 2) + (j >> 1) * 8;
                    int o  = wo * 80 + nt * 8 + (lane & 3) * 2 + (j & 1);
                    if (o <= 144) {
                        float bias = (o < 80) ? __ldg(&cb[o])
                                   : (o < 144) ? __ldg(&rb[o - 80])
                                               : __ldg(ob);
                        int ch = (o == 144) ? 0 : o + 1;
                        stg[px * SP + ch] = acc[mt][nt][j] + bias;
                    }
                }
    }
    __syncthreads();

    // DFL decode + box: 512 tasks (128 px x 4 sides), 2 per thread
    #pragma unroll
    for (int it = 0; it < 2; it++) {
        int task = t + it * 256;
        int m = task >> 2, f = task & 3;
        const float* row = &stg[m * SP + 81 + 16 * f];
        float mx = row[0];
        #pragma unroll
        for (int i = 1; i < 16; i++) mx = fmaxf(mx, row[i]);
        float se = 0.f, sw = 0.f;
        #pragma unroll
        for (int i = 0; i < 16; i++) {
            float ev = __expf(row[i] - mx);
            se += ev;
            sw = fmaf(ev, (float)i, sw);
        }
        float d = (sw / se) * (16.0f / 15.0f);   // proj[i] = i * 16/15
        int mg = m0 + m;
        int hh = mg / W, ww = mg - hh * W;
        float ax = ((float)ww + 0.5f) * stride;
        float ay = ((float)hh + 0.5f) * stride;
        float ds = d * stride;
        float v = (f == 0) ? (ax - ds) : (f == 1) ? (ay - ds)
                : (f == 2) ? (ax + ds) : (ay + ds);
        stg[m * SP + 145 + f] = v;
    }
    __syncthreads();

    float* outp = out + ((size_t)b * 8400 + moff + m0) * 149;
    const int tot = mvalid * 149;
    for (int idx = t; idx < tot; idx += 256) {
        int m = idx / 149, ch = idx - m * 149;
        outp[idx] = stg[m * SP + ch];
    }
}

extern "C" void kernel_launch(void* const* d_in, const int* in_sizes, int n_in,
                              void* d_out, int out_size)
{
    Params P;
    if (in_sizes[1] == in_sizes[0]) {       // dict order cls0,reg0,cls1,reg1,cls2,reg2
        P.clsF[0] = (const float*)d_in[0]; P.regF[0] = (const float*)d_in[1];
        P.clsF[1] = (const float*)d_in[2]; P.regF[1] = (const float*)d_in[3];
        P.clsF[2] = (const float*)d_in[4]; P.regF[2] = (const float*)d_in[5];
    } else {                                // signature order cls0,cls1,cls2,reg0,reg1,reg2
        P.clsF[0] = (const float*)d_in[0]; P.regF[0] = (const float*)d_in[3];
        P.clsF[1] = (const float*)d_in[1]; P.regF[1] = (const float*)d_in[4];
        P.clsF[2] = (const float*)d_in[2]; P.regF[2] = (const float*)d_in[5];
    }
    for (int l = 0; l < 3; l++) {
        P.ow[l] = (const float*)d_in[6  + 6 * l];
        P.ob[l] = (const float*)d_in[7  + 6 * l];
        P.cw[l] = (const float*)d_in[8  + 6 * l];
        P.cb[l] = (const float*)d_in[9  + 6 * l];
        P.rw[l] = (const float*)d_in[10 + 6 * l];
        P.rb[l] = (const float*)d_in[11 + 6 * l];
    }
    int B = in_sizes[0] / (256 * 6400);

    static int configured = 0;
    if (!configured) {
        cudaFuncSetAttribute(pred_mma_kernel, cudaFuncAttributeMaxDynamicSharedMemorySize, SMEM_TOTAL);
        configured = 1;
    }
    dim3 grid(67, B);                       // 50 + 13 + 4 tiles per batch
    pred_mma_kernel<<<grid, 256, SMEM_TOTAL>>>(P, (float*)d_out);
}

// round 4
// speedup vs baseline: 3.4983x; 1.4064x over previous
#include <cuda_runtime.h>
#include <cstdint>

// ---- smem layout (bytes) ----
#define FP      544                  // feat row pitch: 136 floats (128 px + pad)
#define FBUF    8704                 // one tensor chunk: 16 k-rows * 544
#define FSTAGE  17408                // per-stage feat: 2 tensors
#define FOFF    0                    // 3 stages * 17408 = 52224
#define WPITCH  80                   // weight row pitch: 20 floats (16 k + pad)
#define WBUF    12800                // 160 o-rows * 80
#define WOFF    52224                // 3 stages * 12800 = 38400
#define SMEM_TOTAL 90624             // 52224 + 38400 ; x2 CTA = 181248 <= 227KB
#define SP 153                       // epilogue stage pitch (floats); 64*153*4 = 39168 aliases FOFF

struct Params {
    const float* clsF[3]; const float* regF[3];
    const float* ow[3]; const float* ob[3];
    const float* cw[3]; const float* cb[3];
    const float* rw[3]; const float* rb[3];
};

extern __shared__ char smch[];

__device__ __forceinline__ uint32_t smu32(const void* p) {
    uint32_t a;
    asm("{ .reg .u64 t; cvta.to.shared.u64 t, %1; cvt.u32.u64 %0, t; }" : "=r"(a) : "l"(p));
    return a;
}
__device__ __forceinline__ uint32_t lds1(uint32_t a) {
    uint32_t v;
    asm volatile("ld.shared.b32 %0, [%1];" : "=r"(v) : "r"(a));
    return v;
}
__device__ __forceinline__ void mma_tf32(float* d, const uint32_t* a, uint32_t b0, uint32_t b1) {
    asm volatile("mma.sync.aligned.m16n8k8.row.col.f32.tf32.tf32.f32 "
                 "{%0,%1,%2,%3}, {%4,%5,%6,%7}, {%8,%9}, {%0,%1,%2,%3};"
                 : "+f"(d[0]), "+f"(d[1]), "+f"(d[2]), "+f"(d[3])
                 : "r"(a[0]), "r"(a[1]), "r"(a[2]), "r"(a[3]), "r"(b0), "r"(b1));
}
__device__ __forceinline__ void cpa_cg(uint32_t dst, const float* src, int sz) {
    asm volatile("cp.async.cg.shared.global [%0], [%1], 16, %2;"
                 :: "r"(dst), "l"(src), "r"(sz) : "memory");
}
__device__ __forceinline__ void cpa_ca(uint32_t dst, const float* src, int sz) {
    asm volatile("cp.async.ca.shared.global [%0], [%1], 16, %2;"
                 :: "r"(dst), "l"(src), "r"(sz) : "memory");
}

__device__ __forceinline__ void issue_chunk(int c, int st,
        const float* clsF, const float* regF,
        const float* cw, const float* rw, const float* ow,
        uint32_t sb, int M, int m0, int mvalid, int t)
{
    // features: 2 tensors x 16 k-rows x 32 quads of 16B
    #pragma unroll
    for (int it = 0; it < 4; it++) {
        int i = t + it * 256;
        int tensor = i >> 9, r = (i >> 5) & 15, q = i & 31;
        const float* src = (tensor ? regF : clsF) + (size_t)(c * 16 + r) * M + m0 + q * 4;
        uint32_t dst = sb + FOFF + st * FSTAGE + tensor * FBUF + r * FP + q * 16;
        cpa_cg(dst, src, (q * 4 < mvalid) ? 16 : 0);
    }
    // weights: 160 o-rows x 4 quads of 16B (rows 145..159 zero-filled)
    #pragma unroll
    for (int it = 0; it < 3; it++) {
        int i = t + it * 256;
        if (i < 640) {
            int o = i >> 2, q = i & 3;
            const float* src = ow;
            int sz = 0;
            if (o < 80)        { src = cw + o * 256 + c * 16 + q * 4; sz = 16; }
            else if (o < 144)  { src = rw + (o - 80) * 256 + c * 16 + q * 4; sz = 16; }
            else if (o == 144) { src = ow + c * 16 + q * 4; sz = 16; }
            cpa_ca(sb + WOFF + st * WBUF + o * WPITCH + q * 16, src, sz);
        }
    }
    asm volatile("cp.async.commit_group;" ::: "memory");
}

__global__ __launch_bounds__(256, 2) void pred_tf32_kernel(Params P, float* __restrict__ out)
{
    const int t = threadIdx.x, lane = t & 31, wid = t >> 5;
    const int wo = wid >> 1, wpx = wid & 1;     // 4 o-groups x 2 px-groups
    const int tb = blockIdx.x, b = blockIdx.y;

    int l, tile;
    if (tb < 50)      { l = 0; tile = tb; }
    else if (tb < 63) { l = 1; tile = tb - 50; }
    else              { l = 2; tile = tb - 63; }
    const int   Ms[3]    = {6400, 1600, 400};
    const int   Wg[3]    = {80, 40, 20};
    const int   moffs[3] = {0, 6400, 8000};
    const float strs[3]  = {8.f, 16.f, 32.f};
    const int M = Ms[l], W = Wg[l], moff = moffs[l];
    const float stride = strs[l];
    const int m0 = tile * 128;
    const int mvalid = min(128, M - m0);

    const float* clsF = P.clsF[l] + (size_t)b * 256 * M;
    const float* regF = P.regF[l] + (size_t)b * 256 * M;
    const float* cw = P.cw[l];
    const float* rw = P.rw[l];
    const float* ow = P.ow[l];
    const uint32_t sb = smu32(smch);

    // prologue: fill 3-stage pipeline
    issue_chunk(0, 0, clsF, regF, cw, rw, ow, sb, M, m0, mvalid, t);
    issue_chunk(1, 1, clsF, regF, cw, rw, ow, sb, M, m0, mvalid, t);
    issue_chunk(2, 2, clsF, regF, cw, rw, ow, sb, M, m0, mvalid, t);

    float acc[4][5][4];
    #pragma unroll
    for (int mt = 0; mt < 4; mt++)
        #pragma unroll
        for (int nt = 0; nt < 5; nt++)
            #pragma unroll
            for (int j = 0; j < 4; j++) acc[mt][nt][j] = 0.f;

    // per-thread invariant smem offsets
    const uint32_t abase = sb + FOFF + (wo >> 1) * FBUF
                         + (uint32_t)(lane & 3) * FP
                         + (uint32_t)(wpx * 64 + (lane >> 2)) * 4;
    const uint32_t bbase = sb + WOFF
                         + (uint32_t)(wo * 40 + (lane >> 2)) * WPITCH
                         + (uint32_t)(lane & 3) * 4;

    int st = 0;
    for (int c = 0; c < 16; c++) {
        asm volatile("cp.async.wait_group 2;" ::: "memory");
        __syncthreads();

        const uint32_t fb = abase + st * FSTAGE;
        const uint32_t wb = bbase + st * WBUF;
        #pragma unroll
        for (int s = 0; s < 2; s++) {
            uint32_t a[4][4];
            #pragma unroll
            for (int mt = 0; mt < 4; mt++) {
                uint32_t ab = fb + s * (8 * FP) + mt * 64;
                a[mt][0] = lds1(ab);
                a[mt][1] = lds1(ab + 32);
                a[mt][2] = lds1(ab + 4 * FP);
                a[mt][3] = lds1(ab + 4 * FP + 32);
            }
            #pragma unroll
            for (int nt = 0; nt < 5; nt++) {
                uint32_t w2 = wb + s * 32 + nt * (8 * WPITCH);
                uint32_t b0 = lds1(w2), b1 = lds1(w2 + 16);
                #pragma unroll
                for (int mt = 0; mt < 4; mt++) mma_tf32(acc[mt][nt], a[mt], b0, b1);
            }
        }
        __syncthreads();
        if (c + 3 < 16)
            issue_chunk(c + 3, st, clsF, regF, cw, rw, ow, sb, M, m0, mvalid, t);
        else
            asm volatile("cp.async.commit_group;" ::: "memory");
        st = (st == 2) ? 0 : st + 1;
    }

    // ---- epilogue in two 64-px halves (stage aliases feat bufs) ----
    const float* cb = P.cb[l];
    const float* rb = P.rb[l];
    const float* ob = P.ob[l];
    float* stg = reinterpret_cast<float*>(smch);

    for (int h = 0; h < 2; h++) {
        if (wpx == h) {
            #pragma unroll
            for (int mt = 0; mt < 4; mt++)
                #pragma unroll
                for (int nt = 0; nt < 5; nt++)
                    #pragma unroll
                    for (int j = 0; j < 4; j++) {
                        int o = wo * 40 + nt * 8 + (lane & 3) * 2 + (j & 1);
                        if (o <= 144) {
                            int px = mt * 16 + (lane >> 2) + (j >> 1) * 8;
                            float bias = (o < 80)  ? __ldg(&cb[o])
                                       : (o < 144) ? __ldg(&rb[o - 80])
                                                   : __ldg(ob);
                            int ch = (o == 144) ? 0 : o + 1;
                            stg[px * SP + ch] = acc[mt][nt][j] + bias;
                        }
                    }
        }
        __syncthreads();
        // DFL decode + box: 256 tasks (64 px x 4 sides), 1 per thread
        {
            int m = t >> 2, f = t & 3;
            const float* row = &stg[m * SP + 81 + 16 * f];
            float mx = row[0];
            #pragma unroll
            for (int i = 1; i < 16; i++) mx = fmaxf(mx, row[i]);
            float se = 0.f, sw = 0.f;
            #pragma unroll
            for (int i = 0; i < 16; i++) {
                float ev = __expf(row[i] - mx);
                se += ev;
                sw = fmaf(ev, (float)i, sw);
            }
            float d = (sw / se) * (16.0f / 15.0f);   // proj[i] = i * 16/15
            int mg = m0 + h * 64 + m;
            int hh = mg / W, ww = mg - hh * W;
            float ax = ((float)ww + 0.5f) * stride;
            float ay = ((float)hh + 0.5f) * stride;
            float ds = d * stride;
            float v = (f == 0) ? (ax - ds) : (f == 1) ? (ay - ds)
                    : (f == 2) ? (ax + ds) : (ay + ds);
            stg[m * SP + 145 + f] = v;
        }
        __syncthreads();
        int valid = min(64, mvalid - h * 64);
        if (valid > 0) {
            float* outp = out + ((size_t)b * 8400 + moff + m0 + h * 64) * 149;
            for (int idx = t; idx < valid * 149; idx += 256) {
                int m = idx / 149, ch = idx - m * 149;
                outp[idx] = stg[m * SP + ch];
            }
        }
        __syncthreads();
    }
}

extern "C" void kernel_launch(void* const* d_in, const int* in_sizes, int n_in,
                              void* d_out, int out_size)
{
    Params P;
    if (in_sizes[1] == in_sizes[0]) {       // dict order cls0,reg0,cls1,reg1,cls2,reg2
        P.clsF[0] = (const float*)d_in[0]; P.regF[0] = (const float*)d_in[1];
        P.clsF[1] = (const float*)d_in[2]; P.regF[1] = (const float*)d_in[3];
        P.clsF[2] = (const float*)d_in[4]; P.regF[2] = (const float*)d_in[5];
    } else {                                // signature order cls0,cls1,cls2,reg0,reg1,reg2
        P.clsF[0] = (const float*)d_in[0]; P.regF[0] = (const float*)d_in[3];
        P.clsF[1] = (const float*)d_in[1]; P.regF[1] = (const float*)d_in[4];
        P.clsF[2] = (const float*)d_in[2]; P.regF[2] = (const float*)d_in[5];
    }
    for (int l = 0; l < 3; l++) {
        P.ow[l] = (const float*)d_in[6  + 6 * l];
        P.ob[l] = (const float*)d_in[7  + 6 * l];
        P.cw[l] = (const float*)d_in[8  + 6 * l];
        P.cb[l] = (const float*)d_in[9  + 6 * l];
        P.rw[l] = (const float*)d_in[10 + 6 * l];
        P.rb[l] = (const float*)d_in[11 + 6 * l];
    }
    int B = in_sizes[0] / (256 * 6400);

    static int configured = 0;
    if (!configured) {
        cudaFuncSetAttribute(pred_tf32_kernel, cudaFuncAttributeMaxDynamicSharedMemorySize, SMEM_TOTAL);
        configured = 1;
    }
    dim3 grid(67, B);                       // 50 + 13 + 4 tiles per batch
    pred_tf32_kernel<<<grid, 256, SMEM_TOTAL>>>(P, (float*)d_out);
}

// round 5
// speedup vs baseline: 3.6631x; 1.0471x over previous
#include <cuda_runtime.h>
#include <cstdint>

// ---- smem layout (bytes) ----
#define FP      544                  // feat row pitch: 136 floats (128 px + pad)
#define FBUF    8704                 // one tensor chunk: 16 k-rows * 544
#define FSTAGE  17408                // per-stage feat: 2 tensors
#define FOFF    0                    // 3 stages * 17408 = 52224
#define WPITCH  80                   // weight row pitch: 20 floats (16 k + pad)
#define WBUF    12800                // 160 o-rows * 80
#define WOFF    52224                // 3 stages * 12800 = 38400
#define SMEM_TOTAL 90624             // 52224 + 38400 ; x2 CTA = 181248 <= 227KB
#define SP 153                       // epilogue stage pitch (floats); 64*153*4 = 39168 aliases FOFF

struct Params {
    const float* clsF[3]; const float* regF[3];
    const float* ow[3]; const float* ob[3];
    const float* cw[3]; const float* cb[3];
    const float* rw[3]; const float* rb[3];
};

extern __shared__ char smch[];

__device__ __forceinline__ uint32_t smu32(const void* p) {
    uint32_t a;
    asm("{ .reg .u64 t; cvta.to.shared.u64 t, %1; cvt.u32.u64 %0, t; }" : "=r"(a) : "l"(p));
    return a;
}
__device__ __forceinline__ uint32_t lds1(uint32_t a) {
    uint32_t v;
    asm volatile("ld.shared.b32 %0, [%1];" : "=r"(v) : "r"(a));
    return v;
}
__device__ __forceinline__ void mma_tf32(float* d, const uint32_t* a, uint32_t b0, uint32_t b1) {
    asm volatile("mma.sync.aligned.m16n8k8.row.col.f32.tf32.tf32.f32 "
                 "{%0,%1,%2,%3}, {%4,%5,%6,%7}, {%8,%9}, {%0,%1,%2,%3};"
                 : "+f"(d[0]), "+f"(d[1]), "+f"(d[2]), "+f"(d[3])
                 : "r"(a[0]), "r"(a[1]), "r"(a[2]), "r"(a[3]), "r"(b0), "r"(b1));
}
__device__ __forceinline__ void cpa_cg(uint32_t dst, const float* src, int sz) {
    asm volatile("cp.async.cg.shared.global [%0], [%1], 16, %2;"
                 :: "r"(dst), "l"(src), "r"(sz) : "memory");
}
__device__ __forceinline__ void cpa_ca(uint32_t dst, const float* src, int sz) {
    asm volatile("cp.async.ca.shared.global [%0], [%1], 16, %2;"
                 :: "r"(dst), "l"(src), "r"(sz) : "memory");
}

__device__ __forceinline__ void issue_chunk(int c, int st,
        const float* clsF, const float* regF,
        const float* cw, const float* rw, const float* ow,
        uint32_t sb, int M, int m0, int mvalid, int t)
{
    // features: 2 tensors x 16 k-rows x 32 quads of 16B
    #pragma unroll
    for (int it = 0; it < 4; it++) {
        int i = t + it * 256;
        int tensor = i >> 9, r = (i >> 5) & 15, q = i & 31;
        const float* src = (tensor ? regF : clsF) + (size_t)(c * 16 + r) * M + m0 + q * 4;
        uint32_t dst = sb + FOFF + st * FSTAGE + tensor * FBUF + r * FP + q * 16;
        cpa_cg(dst, src, (q * 4 < mvalid) ? 16 : 0);
    }
    // weights: 160 o-rows x 4 quads of 16B (rows 145..159 zero-filled)
    #pragma unroll
    for (int it = 0; it < 3; it++) {
        int i = t + it * 256;
        if (i < 640) {
            int o = i >> 2, q = i & 3;
            const float* src = ow;
            int sz = 0;
            if (o < 80)        { src = cw + o * 256 + c * 16 + q * 4; sz = 16; }
            else if (o < 144)  { src = rw + (o - 80) * 256 + c * 16 + q * 4; sz = 16; }
            else if (o == 144) { src = ow + c * 16 + q * 4; sz = 16; }
            cpa_ca(sb + WOFF + st * WBUF + o * WPITCH + q * 16, src, sz);
        }
    }
    asm volatile("cp.async.commit_group;" ::: "memory");
}

__global__ __launch_bounds__(256, 2) void pred_tf32_kernel(Params P, float* __restrict__ out)
{
    const int t = threadIdx.x, lane = t & 31, wid = t >> 5;
    const int wo = wid >> 1, wpx = wid & 1;     // 4 o-groups x 2 px-groups
    const int tb = blockIdx.x, b = blockIdx.y;

    int l, tile;
    if (tb < 50)      { l = 0; tile = tb; }
    else if (tb < 63) { l = 1; tile = tb - 50; }
    else              { l = 2; tile = tb - 63; }
    const int   Ms[3]    = {6400, 1600, 400};
    const int   Wg[3]    = {80, 40, 20};
    const int   moffs[3] = {0, 6400, 8000};
    const float strs[3]  = {8.f, 16.f, 32.f};
    const int M = Ms[l], W = Wg[l], moff = moffs[l];
    const float stride = strs[l];
    const int m0 = tile * 128;
    const int mvalid = min(128, M - m0);

    const float* clsF = P.clsF[l] + (size_t)b * 256 * M;
    const float* regF = P.regF[l] + (size_t)b * 256 * M;
    const float* cw = P.cw[l];
    const float* rw = P.rw[l];
    const float* ow = P.ow[l];
    const uint32_t sb = smu32(smch);

    // prologue: fill 2 of 3 pipeline stages
    issue_chunk(0, 0, clsF, regF, cw, rw, ow, sb, M, m0, mvalid, t);
    issue_chunk(1, 1, clsF, regF, cw, rw, ow, sb, M, m0, mvalid, t);

    float acc[4][5][4];
    #pragma unroll
    for (int mt = 0; mt < 4; mt++)
        #pragma unroll
        for (int nt = 0; nt < 5; nt++)
            #pragma unroll
            for (int j = 0; j < 4; j++) acc[mt][nt][j] = 0.f;

    // per-thread invariant smem offsets
    const uint32_t abase = sb + FOFF + (wo >> 1) * FBUF
                         + (uint32_t)(lane & 3) * FP
                         + (uint32_t)(wpx * 64 + (lane >> 2)) * 4;
    const uint32_t bbase = sb + WOFF
                         + (uint32_t)(wo * 40 + (lane >> 2)) * WPITCH
                         + (uint32_t)(lane & 3) * 4;

    int st = 0, ist = 2;
    #pragma unroll 1
    for (int c = 0; c < 16; c++) {
        // chunk c resident once <=1 newer group outstanding (empty tail commits
        // below keep the group numbering uniform through the last iterations)
        asm volatile("cp.async.wait_group 1;" ::: "memory");
        __syncthreads();   // publishes stage st to all warps; frees stage ist

        if (c + 2 < 16)
            issue_chunk(c + 2, ist, clsF, regF, cw, rw, ow, sb, M, m0, mvalid, t);
        else
            asm volatile("cp.async.commit_group;" ::: "memory");

        const uint32_t fb = abase + st * FSTAGE;
        const uint32_t wb = bbase + st * WBUF;
        #pragma unroll
        for (int s = 0; s < 2; s++) {
            uint32_t a[4][4];
            #pragma unroll
            for (int mt = 0; mt < 4; mt++) {
                uint32_t ab = fb + s * (8 * FP) + mt * 64;
                a[mt][0] = lds1(ab);
                a[mt][1] = lds1(ab + 32);
                a[mt][2] = lds1(ab + 4 * FP);
                a[mt][3] = lds1(ab + 4 * FP + 32);
            }
            #pragma unroll
            for (int nt = 0; nt < 5; nt++) {
                uint32_t w2 = wb + s * 32 + nt * (8 * WPITCH);
                uint32_t b0 = lds1(w2), b1 = lds1(w2 + 16);
                #pragma unroll
                for (int mt = 0; mt < 4; mt++) mma_tf32(acc[mt][nt], a[mt], b0, b1);
            }
        }
        st  = (st  == 2) ? 0 : st  + 1;
        ist = (ist == 2) ? 0 : ist + 1;
    }
    __syncthreads();   // last compute done everywhere before stage alias reuse

    // ---- epilogue in two 64-px halves (stage aliases feat bufs) ----
    const float* cb = P.cb[l];
    const float* rb = P.rb[l];
    const float* ob = P.ob[l];
    float* stg = reinterpret_cast<float*>(smch);

    for (int h = 0; h < 2; h++) {
        if (wpx == h) {
            #pragma unroll
            for (int mt = 0; mt < 4; mt++)
                #pragma unroll
                for (int nt = 0; nt < 5; nt++)
                    #pragma unroll
                    for (int j = 0; j < 4; j++) {
                        int o = wo * 40 + nt * 8 + (lane & 3) * 2 + (j & 1);
                        if (o <= 144) {
                            int px = mt * 16 + (lane >> 2) + (j >> 1) * 8;
                            float bias = (o < 80)  ? __ldg(&cb[o])
                                       : (o < 144) ? __ldg(&rb[o - 80])
                                                   : __ldg(ob);
                            int ch = (o == 144) ? 0 : o + 1;
                            stg[px * SP + ch] = acc[mt][nt][j] + bias;
                        }
                    }
        }
        __syncthreads();
        // DFL decode + box: 256 tasks (64 px x 4 sides), 1 per thread
        {
            int m = t >> 2, f = t & 3;
            const float* row = &stg[m * SP + 81 + 16 * f];
            float mx = row[0];
            #pragma unroll
            for (int i = 1; i < 16; i++) mx = fmaxf(mx, row[i]);
            float se = 0.f, sw = 0.f;
            #pragma unroll
            for (int i = 0; i < 16; i++) {
                float ev = __expf(row[i] - mx);
                se += ev;
                sw = fmaf(ev, (float)i, sw);
            }
            float d = (sw / se) * (16.0f / 15.0f);   // proj[i] = i * 16/15
            int mg = m0 + h * 64 + m;
            int hh = mg / W, ww = mg - hh * W;
            float ax = ((float)ww + 0.5f) * stride;
            float ay = ((float)hh + 0.5f) * stride;
            float ds = d * stride;
            float v = (f == 0) ? (ax - ds) : (f == 1) ? (ay - ds)
                    : (f == 2) ? (ax + ds) : (ay + ds);
            stg[m * SP + 145 + f] = v;
        }
        __syncthreads();
        int valid = min(64, mvalid - h * 64);
        if (valid > 0) {
            float* outp = out + ((size_t)b * 8400 + moff + m0 + h * 64) * 149;
            for (int idx = t; idx < valid * 149; idx += 256) {
                int m = idx / 149, ch = idx - m * 149;
                outp[idx] = stg[m * SP + ch];
            }
        }
        __syncthreads();
    }
}

extern "C" void kernel_launch(void* const* d_in, const int* in_sizes, int n_in,
                              void* d_out, int out_size)
{
    Params P;
    if (in_sizes[1] == in_sizes[0]) {       // dict order cls0,reg0,cls1,reg1,cls2,reg2
        P.clsF[0] = (const float*)d_in[0]; P.regF[0] = (const float*)d_in[1];
        P.clsF[1] = (const float*)d_in[2]; P.regF[1] = (const float*)d_in[3];
        P.clsF[2] = (const float*)d_in[4]; P.regF[2] = (const float*)d_in[5];
    } else {                                // signature order cls0,cls1,cls2,reg0,reg1,reg2
        P.clsF[0] = (const float*)d_in[0]; P.regF[0] = (const float*)d_in[3];
        P.clsF[1] = (const float*)d_in[1]; P.regF[1] = (const float*)d_in[4];
        P.clsF[2] = (const float*)d_in[2]; P.regF[2] = (const float*)d_in[5];
    }
    for (int l = 0; l < 3; l++) {
        P.ow[l] = (const float*)d_in[6  + 6 * l];
        P.ob[l] = (const float*)d_in[7  + 6 * l];
        P.cw[l] = (const float*)d_in[8  + 6 * l];
        P.cb[l] = (const float*)d_in[9  + 6 * l];
        P.rw[l] = (const float*)d_in[10 + 6 * l];
        P.rb[l] = (const float*)d_in[11 + 6 * l];
    }
    int B = in_sizes[0] / (256 * 6400);

    static int configured = 0;
    if (!configured) {
        cudaFuncSetAttribute(pred_tf32_kernel, cudaFuncAttributeMaxDynamicSharedMemorySize, SMEM_TOTAL);
        configured = 1;
    }
    dim3 grid(67, B);                       // 50 + 13 + 4 tiles per batch
    pred_tf32_kernel<<<grid, 256, SMEM_TOTAL>>>(P, (float*)d_out);
}